// round 7
// baseline (speedup 1.0000x reference)
#include <cuda_runtime.h>
#include <cuda_bf16.h>

// LocalitySensitiveHashing_29111288333011 — FINAL FORM
//
// Mathematical collapse (holds for ALL inputs, provable from the reference's
// constants alone): the 'bqhk,bkhk->bhqk' einsum has no contracted index
// (the repeated k on 'bkhk' is a diagonal extraction), so sim is an
// elementwise product of sign() values in {-1,0,+1}, scaled by 1/hash_bits
// (HB=2048) and averaged over H=8 heads:
//     |sim[b,q,k]| <= 1/HB = 4.88e-4  <  SIM_THRESHOLD = 0.3
// => (sim > 0.3) is identically False => output == zeros([2,2048,2048], f32).
// The optimal kernel is a pure 32 MiB zero-fill; no input is read.
//
// Measured floor (5-path experiment matrix, R1-R6): per-lane STG.128 (x1 and
// x8 per thread), driver memset node, TMA bulk store, and STG.256 all pin at
// ~4.3-4.5 TB/s with DRAM=0% — the chip-level L2-write cap at bench clocks.
// Best kernel: STG.128 + .cs evict-first (7.456 us). e2e floor 8.672 us =
// store wall + fixed graph-replay overhead (insensitive to +-0.4us kernel
// deltas). This file is the empirically best configuration.

#define ZF_THREADS 256
#define ZF_V       8                       // float4 per thread
#define ZF_TILE    (ZF_THREADS * ZF_V)     // 2048 float4 per block

__global__ __launch_bounds__(ZF_THREADS)
void lsh_zero_exact_kernel(float4* __restrict__ out) {
    // Exact-cover launch: no bounds checks on the hot path.
    unsigned int base = blockIdx.x * ZF_TILE + threadIdx.x;
    const float4 z = make_float4(0.0f, 0.0f, 0.0f, 0.0f);
    #pragma unroll
    for (int j = 0; j < ZF_V; j++) {
        __stcs(out + base + j * ZF_THREADS, z);   // st.global.cs.v4 (streaming)
    }
}

// Generic tail (never launched for this shape; kept for robustness).
__global__ void lsh_zero_tail_kernel(float* __restrict__ out, long long n) {
    long long i = (long long)blockIdx.x * blockDim.x + threadIdx.x;
    if (i < n) out[i] = 0.0f;
}

extern "C" void kernel_launch(void* const* d_in, const int* in_sizes, int n_in,
                              void* d_out, int out_size) {
    (void)d_in; (void)in_sizes; (void)n_in;

    float* out = (float*)d_out;
    long long n = (long long)out_size;        // 8,388,608 floats (32 MiB)

    long long n4      = n >> 2;               // float4 count
    long long blocks  = n4 / ZF_TILE;         // 1024 exact-cover blocks
    long long covered = blocks * (long long)ZF_TILE * 4;

    if (blocks > 0) {
        lsh_zero_exact_kernel<<<(unsigned int)blocks, ZF_THREADS>>>((float4*)out);
    }
    long long rem = n - covered;              // 0 for this shape
    if (rem > 0) {
        long long tb = (rem + 255) / 256;
        lsh_zero_tail_kernel<<<(unsigned int)tb, 256>>>(out + covered, rem);
    }
}

// round 8
// speedup vs baseline: 1.0772x; 1.0772x over previous
#include <cuda_runtime.h>
#include <cuda_bf16.h>

// LocalitySensitiveHashing_29111288333011 — FINAL FORM (canonical best)
//
// Mathematical collapse (holds for ALL inputs, provable from the reference's
// constants alone): the 'bqhk,bkhk->bhqk' einsum has no contracted index
// (the repeated k on 'bkhk' is a diagonal extraction), so sim is an
// elementwise product of sign() values in {-1,0,+1}, scaled by 1/hash_bits
// (HB=2048) and averaged over H=8 heads:
//     |sim[b,q,k]| <= 1/HB = 4.88e-4  <  SIM_THRESHOLD = 0.3
// => (sim > 0.3) is identically False => output == zeros([2,2048,2048], f32).
// The optimal kernel is a pure 32 MiB zero-fill; no input is read.
//
// Experiment matrix (R1-R7): per-lane STG.128 (x1, x8/thread), STG.256,
// driver memset node, TMA bulk store, .cs vs default policy, two grid
// shapes, plus an identical-config rerun establishing run-to-run noise of
// +-0.4us kernel / +-0.7us e2e. All configurations are statistically
// indistinguishable at kernel 7.4-7.9us (~4.3-4.5 TB/s, DRAM=0%): the
// chip-level L2-write cap at bench clocks. e2e floor ~8.7us = wall + fixed
// graph-replay overhead. This file is the canonical best configuration.

#define ZF_THREADS 256
#define ZF_V       8                       // float4 per thread
#define ZF_TILE    (ZF_THREADS * ZF_V)     // 2048 float4 per block

__global__ __launch_bounds__(ZF_THREADS)
void lsh_zero_exact_kernel(float4* __restrict__ out) {
    // Exact-cover launch: no bounds checks on the hot path.
    unsigned int base = blockIdx.x * ZF_TILE + threadIdx.x;
    const float4 z = make_float4(0.0f, 0.0f, 0.0f, 0.0f);
    #pragma unroll
    for (int j = 0; j < ZF_V; j++) {
        __stcs(out + base + j * ZF_THREADS, z);   // st.global.cs.v4 (streaming)
    }
}

// Generic tail (never launched for this shape; kept for robustness).
__global__ void lsh_zero_tail_kernel(float* __restrict__ out, long long n) {
    long long i = (long long)blockIdx.x * blockDim.x + threadIdx.x;
    if (i < n) out[i] = 0.0f;
}

extern "C" void kernel_launch(void* const* d_in, const int* in_sizes, int n_in,
                              void* d_out, int out_size) {
    (void)d_in; (void)in_sizes; (void)n_in;

    float* out = (float*)d_out;
    long long n = (long long)out_size;        // 8,388,608 floats (32 MiB)

    long long n4      = n >> 2;               // float4 count
    long long blocks  = n4 / ZF_TILE;         // 1024 exact-cover blocks
    long long covered = blocks * (long long)ZF_TILE * 4;

    if (blocks > 0) {
        lsh_zero_exact_kernel<<<(unsigned int)blocks, ZF_THREADS>>>((float4*)out);
    }
    long long rem = n - covered;              // 0 for this shape
    if (rem > 0) {
        long long tb = (rem + 255) / 256;
        lsh_zero_tail_kernel<<<(unsigned int)tb, 256>>>(out + covered, rem);
    }
}